// round 16
// baseline (speedup 1.0000x reference)
#include <cuda_runtime.h>
#include <cuda_fp16.h>
#include <stdint.h>

#define BSZ   1024
#define NDIM  1024
#define TLEN  100

// d_out layout (float elements)
#define OFF_ACT 0
#define OFF_E3H 2048
#define OFF_E5H (2048 + 102400)
#define OFF_C1H (2048 + 2*102400)
#define OFF_EC3 (2048 + 3*102400)
#define OFF_EC5 (OFF_EC3 + 1048576)
#define OFF_CA1 (OFF_EC5 + 1048576)

// Activations/weights: k-tile-major swizzled fp16 (validated R15 layout)
__device__ float    g_drive[TLEN * NDIM];
__device__ uint32_t g_keys[2 * TLEN];
__device__ __half   g_wt1[NDIM * NDIM];
__device__ __half   g_wt2[NDIM * NDIM];
__device__ __half   g_at1[NDIM * NDIM];
__device__ __half   g_at2[NDIM * NDIM];
__device__ unsigned g_bar_count;
__device__ unsigned g_bar_gen;

#define KTILES  8
#define SLAB    131072
#define A_BYTES 32768
#define B_BYTES 16384
#define STAGE_BYTES (A_BYTES + B_BYTES)
#define SM_BAR  (3 * STAGE_BYTES)
#define SMEM_DYN (SM_BAR + 64)
#define NCTA 128

__device__ __forceinline__ size_t sw_idx(int row, int col) {
    int kt = col >> 7, c = (col & 127) >> 3, w = col & 7;
    return (size_t)kt * SLAB + (size_t)row * 128 + (size_t)(((c ^ (row & 7)) << 3) + w);
}

// ---------------------------------------------------------------------------
__device__ __forceinline__ float tf32r(float x) {
    uint32_t u = __float_as_uint(x);
    asm("cvt.rna.tf32.f32 %0, %0;" : "+r"(u));
    return __uint_as_float(u);
}
__device__ __forceinline__ float sigmoidf(float x) { return 1.0f / (1.0f + expf(-x)); }
__device__ __forceinline__ uint32_t smem_to_u32(const void* p) {
    uint32_t a;
    asm("{ .reg .u64 t; cvta.to.shared.u64 t, %1; cvt.u32.u64 %0, t; }" : "=r"(a) : "l"(p));
    return a;
}
#define MBARRIER_INIT(mbar, count) \
    asm volatile("mbarrier.init.shared.b64 [%0], %1;" :: "r"((uint32_t)(mbar)), "r"((uint32_t)(count)) : "memory")
#define MBARRIER_EXPECT_TX(mbar, bytes) \
    asm volatile("mbarrier.arrive.expect_tx.shared.b64 _, [%0], %1;" :: "r"((uint32_t)(mbar)), "r"((uint32_t)(bytes)) : "memory")
#define MBARRIER_WAIT_PARITY(mbar, parity) do { \
    uint32_t _m = (uint32_t)(mbar), _p = (uint32_t)(parity), _d; \
    asm volatile("{\n\t.reg .pred p;\n\t" \
        "mbarrier.try_wait.parity.acquire.cta.shared::cta.b64 p, [%1], %2;\n\t" \
        "selp.b32 %0, 1, 0, p;\n\t}" : "=r"(_d) : "r"(_m), "r"(_p) : "memory"); \
    if (!_d) { \
        asm volatile("{\n\t.reg .pred P1;\n\t" \
            "WL_%=:\n\t" \
            "mbarrier.try_wait.parity.acquire.cta.shared::cta.b64 P1, [%0], %1, 0x989680;\n\t" \
            "@P1 bra.uni WD_%=;\n\t" \
            "bra.uni WL_%=;\n\t" \
            "WD_%=:\n\t}" :: "r"(_m), "r"(_p) : "memory"); \
    } \
} while (0)
__device__ __forceinline__ void bulk_g2s(uint32_t dst, const void* src, uint32_t bytes, uint32_t mbar) {
    asm volatile("cp.async.bulk.shared::cta.global.mbarrier::complete_tx::bytes [%0], [%1], %2, [%3];"
        :: "r"(dst), "l"(src), "r"(bytes), "r"(mbar) : "memory");
}
__device__ __forceinline__ void ldsm4(uint32_t r[4], uint32_t addr) {
    asm volatile("ldmatrix.sync.aligned.m8n8.x4.shared.b16 {%0,%1,%2,%3}, [%4];"
        : "=r"(r[0]), "=r"(r[1]), "=r"(r[2]), "=r"(r[3]) : "r"(addr));
}
__device__ __forceinline__ void mma16(float c[4], const uint32_t a[4],
                                      uint32_t b0, uint32_t b1) {
    asm volatile(
        "mma.sync.aligned.m16n8k16.row.col.f32.f16.f16.f32 "
        "{%0,%1,%2,%3}, {%4,%5,%6,%7}, {%8,%9}, {%0,%1,%2,%3};"
        : "+f"(c[0]), "+f"(c[1]), "+f"(c[2]), "+f"(c[3])
        : "r"(a[0]), "r"(a[1]), "r"(a[2]), "r"(a[3]), "r"(b0), "r"(b1));
}

// ---------------------------------------------------------------------------
// Threefry-2x32 (jax partitionable) — validated
// ---------------------------------------------------------------------------
__device__ __forceinline__ void threefry2x32(uint32_t k0, uint32_t k1,
                                             uint32_t x0, uint32_t x1,
                                             uint32_t& o0, uint32_t& o1) {
    uint32_t ks2 = k0 ^ k1 ^ 0x1BD11BDAu;
    x0 += k0; x1 += k1;
#define TF_R(r) { x0 += x1; x1 = __funnelshift_l(x1, x1, (r)); x1 ^= x0; }
    TF_R(13) TF_R(15) TF_R(26) TF_R(6)
    x0 += k1;  x1 += ks2 + 1u;
    TF_R(17) TF_R(29) TF_R(16) TF_R(24)
    x0 += ks2; x1 += k0 + 2u;
    TF_R(13) TF_R(15) TF_R(26) TF_R(6)
    x0 += k0;  x1 += k1 + 3u;
    TF_R(17) TF_R(29) TF_R(16) TF_R(24)
    x0 += k1;  x1 += ks2 + 4u;
    TF_R(13) TF_R(15) TF_R(26) TF_R(6)
    x0 += ks2; x1 += k0 + 5u;
#undef TF_R
    o0 = x0; o1 = x1;
}

__device__ __forceinline__ bool noise_hit(uint32_t k0, uint32_t k1, uint32_t idx) {
    uint32_t o0, o1;
    threefry2x32(k0, k1, 0u, idx, o0, o1);
    uint32_t bits = o0 ^ o1;
    float u = __uint_as_float((bits >> 9) | 0x3f800000u) - 1.0f;
    return u < 0.004f;
}

// ---------------------------------------------------------------------------
// prep kernel: one-time work in one launch (also resets the global barrier)
// ---------------------------------------------------------------------------
__global__ __launch_bounds__(256) void prep_kernel(
    const float* __restrict__ wec3ca1, const float* __restrict__ wca1ec5,
    const float* __restrict__ ec3_last, const float* __restrict__ ec5_last,
    const float* __restrict__ wca3ca1,
    float* __restrict__ ec3, float* __restrict__ ec5)
{
    __shared__ float tile[32][33];
    __shared__ float ca3[NDIM];
    const int blk = blockIdx.x;
    const int tid = threadIdx.x;

    if (blk < 2048) {                        // weight transposes -> swizzled fp16
        const float* W = (blk < 1024) ? wec3ca1 : wca1ec5;
        __half* dst    = (blk < 1024) ? g_wt1  : g_wt2;
        int b = blk & 1023;
        int bx = (b & 31) * 32, by = (b >> 5) * 32;
        int x = tid & 31, y = tid >> 5;
#pragma unroll
        for (int i = 0; i < 32; i += 8)
            tile[y + i][x] = W[(size_t)(by + y + i) * NDIM + bx + x];
        __syncthreads();
#pragma unroll
        for (int i = 0; i < 32; i += 8) {
            int n = bx + y + i, k = by + x;
            dst[sw_idx(n, k)] = __float2half(tile[x][y + i]);
        }
    } else if (blk < 3072) {                 // ec3 init + swizzled fp16 copy
        int i = ((blk - 2048) * 256 + tid) * 4;
        int m = i >> 10, n = i & 1023;
        float4 v = *(const float4*)(ec3_last + i);
        *(float4*)(ec3 + i) = v;
        g_at1[sw_idx(m, n + 0)] = __float2half(v.x);
        g_at1[sw_idx(m, n + 1)] = __float2half(v.y);
        g_at1[sw_idx(m, n + 2)] = __float2half(v.z);
        g_at1[sw_idx(m, n + 3)] = __float2half(v.w);
    } else if (blk < 4096) {                 // ec5 init
        int i = ((blk - 3072) * 256 + tid) * 4;
        *(float4*)(ec5 + i) = *(const float4*)(ec5_last + i);
    } else if (blk < 4196) {                 // drive rows (tf32-emulated fp32)
        const int t = blk - 4096;
        const float x = (float)t;
        for (int c = tid; c < NDIM; c += 256) {
            float center = (100.0f / 1023.0f) * (float)c;
            float d = center - x;
            ca3[c] = tf32r(expf(-(d * d) / 50.0f));
        }
        __syncthreads();
        for (int n = tid; n < NDIM; n += 256) {
            float acc = 0.0f;
            for (int k = 0; k < NDIM; k++)
                acc += ca3[k] * tf32r(wca3ca1[k * NDIM + n]);
            g_drive[t * NDIM + n] = acc;
        }
    } else {                                 // keys + barrier reset
        if (tid < TLEN) {
            uint32_t o0, o1;
            threefry2x32(0u, 42u, 0u, (uint32_t)tid, o0, o1);
            g_keys[2 * tid] = o0; g_keys[2 * tid + 1] = o1;
        }
        if (tid == 128) { g_bar_count = 0u; g_bar_gen = 0u; }
    }
}

// ---------------------------------------------------------------------------
// global barrier: all 128 CTAs resident (1/SM) -> safe sense-forward barrier
// ---------------------------------------------------------------------------
__device__ __forceinline__ void gbar(unsigned& target) {
    __threadfence();
    __syncthreads();
    if (threadIdx.x == 0) {
        target += 1u;
        unsigned a = atomicAdd(&g_bar_count, 1u);
        if (a == NCTA - 1u) {
            g_bar_count = 0u;
            __threadfence();
            atomicExch(&g_bar_gen, target);
        } else {
            while (atomicAdd(&g_bar_gen, 0u) < target) __nanosleep(32);
        }
        __threadfence();
    }
    __syncthreads();
}

// ---------------------------------------------------------------------------
// one fused GEMM pass; NOISE variant computes the threefry mask in-loop
// ---------------------------------------------------------------------------
template<bool NOISE>
__device__ __forceinline__ void gemm_run(
    const __half* __restrict__ A, const __half* __restrict__ Bt,
    uint32_t sb, uint32_t bar, int m0, int n0, int g,
    const uint32_t abase[2], const uint32_t axr[2], uint32_t aq,
    const uint32_t bbase[2], const uint32_t bxr[2], uint32_t bq,
    float acc[2][4][4], uint32_t nk0, uint32_t nk1, uint32_t& nmask,
    int wm, int wn, int group, int tig)
{
    const int tid = threadIdx.x;
#pragma unroll
    for (int mi = 0; mi < 2; mi++)
#pragma unroll
        for (int nj = 0; nj < 4; nj++)
#pragma unroll
            for (int c = 0; c < 4; c++) acc[mi][nj][c] = 0.0f;

    if (tid == 0) {
#pragma unroll
        for (int kt = 0; kt < 2; kt++) {
            uint32_t mb = bar + kt * 8;
            uint32_t st = sb + kt * STAGE_BYTES;
            MBARRIER_EXPECT_TX(mb, STAGE_BYTES);
            bulk_g2s(st,           A  + (size_t)kt * SLAB + (size_t)m0 * 128, A_BYTES, mb);
            bulk_g2s(st + A_BYTES, Bt + (size_t)kt * SLAB + (size_t)n0 * 128, B_BYTES, mb);
        }
    }

    for (int kt = 0; kt < KTILES; kt++) {
        const int s = kt % 3, u = kt / 3;
        // stage use-count parity across gemm calls: stages 0,1 flip 3x/gemm, stage 2 flips 2x
        const uint32_t par = (s < 2) ? (uint32_t)((g + u) & 1) : (uint32_t)(u & 1);
        MBARRIER_WAIT_PARITY(bar + s * 8, par);
        const uint32_t st = sb + (uint32_t)s * STAGE_BYTES;

#pragma unroll
        for (int kk = 0; kk < 8; kk++) {
            uint32_t af[2][4], b01[4], b23[4];
            const uint32_t ac = 2 * kk + aq;
            const uint32_t bc = 2 * kk + bq;
            ldsm4(af[0], st + abase[0] + (((ac ^ axr[0]) << 4)));
            ldsm4(af[1], st + abase[1] + (((ac ^ axr[1]) << 4)));
            ldsm4(b01,   st + bbase[0] + (((bc ^ bxr[0]) << 4)));
            ldsm4(b23,   st + bbase[1] + (((bc ^ bxr[1]) << 4)));
#pragma unroll
            for (int mi = 0; mi < 2; mi++) {
                mma16(acc[mi][0], af[mi], b01[0], b01[1]);
                mma16(acc[mi][1], af[mi], b01[2], b01[3]);
                mma16(acc[mi][2], af[mi], b23[0], b23[1]);
                mma16(acc[mi][3], af[mi], b23[2], b23[3]);
            }
        }
        if (NOISE) {
            // 4 hashes per k-tile, riding the idle issue slots of the mma wall
#pragma unroll
            for (int h = 0; h < 4; h++) {
                const int e = kt * 4 + h;
                const int mi = e >> 4, nj = (e >> 2) & 3, c = e & 3;
                const int m = m0 + wm * 32 + mi * 16 + group + ((c & 2) ? 8 : 0);
                const int n = n0 + wn * 32 + nj * 8 + tig * 2 + (c & 1);
                if (noise_hit(nk0, nk1, (uint32_t)(m * NDIM + n))) nmask |= (1u << e);
            }
        }
        __syncthreads();
        if (kt + 2 < KTILES && tid == 0) {
            const int kn = kt + 2, sn = kn % 3;
            uint32_t mb = bar + sn * 8;
            uint32_t sd = sb + (uint32_t)sn * STAGE_BYTES;
            MBARRIER_EXPECT_TX(mb, STAGE_BYTES);
            bulk_g2s(sd,           A  + (size_t)kn * SLAB + (size_t)m0 * 128, A_BYTES, mb);
            bulk_g2s(sd + A_BYTES, Bt + (size_t)kn * SLAB + (size_t)n0 * 128, B_BYTES, mb);
        }
    }
}

// ---------------------------------------------------------------------------
// persistent kernel: all 100 steps, 2 GEMMs each, 2 global barriers per step
// ---------------------------------------------------------------------------
__global__ __launch_bounds__(256, 1) void rnn_persistent(
    const float* __restrict__ ca1bias, const int* __restrict__ cue,
    float* __restrict__ ec3, float* __restrict__ ec5,
    float* __restrict__ e3h, float* __restrict__ e5h,
    float* __restrict__ c1h, float* __restrict__ ca1)
{
    extern __shared__ char smp[];
    const uint32_t sb = smem_to_u32(smp);
    const uint32_t bar = sb + SM_BAR;
    const int tid = threadIdx.x;
    const int lane = tid & 31, warp = tid >> 5;
    const int wm = warp & 3, wn = warp >> 2;
    const int group = lane >> 2, tig = lane & 3;
    const int cta = blockIdx.x;
    const int n0 = (cta & 15) * 64, m0 = (cta >> 4) * 128;

    if (tid == 0) {
        MBARRIER_INIT(bar + 0, 1);
        MBARRIER_INIT(bar + 8, 1);
        MBARRIER_INIT(bar + 16, 1);
    }
    __syncthreads();

    // fragment address precompute (R15-validated swizzled 256B rows)
    const int q = lane >> 3, r = lane & 7;
    uint32_t abase[2], axr[2];
    const uint32_t aq = (q & 2) ? 1u : 0u;
#pragma unroll
    for (int mi = 0; mi < 2; mi++) {
        int rowA = wm * 32 + mi * 16 + r + ((q & 1) ? 8 : 0);
        abase[mi] = (uint32_t)(rowA * 256);
        axr[mi] = (uint32_t)(rowA & 7);
    }
    uint32_t bbase[2], bxr[2];
    const uint32_t bq = (q & 1) ? 1u : 0u;
#pragma unroll
    for (int j = 0; j < 2; j++) {
        int rowB = wn * 32 + j * 16 + r + ((q & 2) ? 8 : 0);
        bbase[j] = (uint32_t)(A_BYTES + rowB * 256);
        bxr[j] = (uint32_t)(rowB & 7);
    }

    unsigned bar_target = 0;
    uint32_t dummy_mask = 0;

    for (int t = 0; t < TLEN; t++) {
        float acc[2][4][4];

        // ---- GEMM1 + epilogue1 ----
        gemm_run<false>(g_at1, g_wt1, sb, bar, m0, n0, 2 * t,
                        abase, axr, aq, bbase, bxr, bq,
                        acc, 0u, 0u, dummy_mask, wm, wn, group, tig);
        {
            const float* drive = &g_drive[t * NDIM];
            const bool last = (t == TLEN - 1);
#pragma unroll
            for (int mi = 0; mi < 2; mi++)
#pragma unroll
                for (int nj = 0; nj < 4; nj++)
#pragma unroll
                    for (int c = 0; c < 4; c++) {
                        const int m = m0 + wm * 32 + mi * 16 + group + ((c & 2) ? 8 : 0);
                        const int n = n0 + wn * 32 + nj * 8 + tig * 2 + (c & 1);
                        float v = fmaxf(drive[n] * (1.0f + sigmoidf(acc[mi][nj][c])) - ca1bias[n], 0.0f);
                        if (last) ca1[m * NDIM + n] = v;
                        g_at2[sw_idx(m, n)] = __float2half(v);
                        if (m == 0) c1h[t * NDIM + n] = v;
                    }
        }
        gbar(bar_target);

        // ---- GEMM2 (with in-loop threefry) + epilogue2 ----
        const uint32_t k0 = g_keys[2 * t], k1 = g_keys[2 * t + 1];
        uint32_t nmask = 0;
        gemm_run<true>(g_at2, g_wt2, sb, bar, m0, n0, 2 * t + 1,
                       abase, axr, aq, bbase, bxr, bq,
                       acc, k0, k1, nmask, wm, wn, group, tig);
        {
            const bool at_cue = (t == 10);
#pragma unroll
            for (int mi = 0; mi < 2; mi++)
#pragma unroll
                for (int nj = 0; nj < 4; nj++)
#pragma unroll
                    for (int c = 0; c < 4; c++) {
                        const int e = mi * 16 + nj * 4 + c;
                        const int m = m0 + wm * 32 + mi * 16 + group + ((c & 2) ? 8 : 0);
                        const int n = n0 + wn * 32 + nj * 8 + tig * 2 + (c & 1);
                        const int gi = m * NDIM + n;
                        float e5 = ec5[gi] + acc[mi][nj][c];   // 10*TS == 1.0 exactly
                        e5 = 0.69f + 0.3f * sigmoidf(4.0f * (e5 - 0.3f));
                        float e3 = e5 * ec3[gi];
                        if (at_cue && (cue[gi] != 0)) e3 = 0.4f * e3 + 0.6f;
                        if ((nmask >> e) & 1u) e3 = 0.5f * e3 + 0.3f;
                        ec5[gi] = e5;
                        ec3[gi] = e3;
                        g_at1[sw_idx(m, n)] = __float2half(e3);
                        if (m == 0) { e5h[t * NDIM + n] = e5; e3h[t * NDIM + n] = e3; }
                    }
        }
        gbar(bar_target);
    }
}

// ---------------------------------------------------------------------------
// act_cell = ca1 @ wca1act + actbias (tf32 operands, validated)
// ---------------------------------------------------------------------------
__global__ __launch_bounds__(128) void act_kernel(
    const float* __restrict__ ca1, const float* __restrict__ w,
    const float* __restrict__ bias, float* __restrict__ out)
{
    __shared__ float s0[128], s1[128];
    const int b = blockIdx.x;
    float a0 = 0.0f, a1 = 0.0f;
    for (int c = threadIdx.x; c < NDIM; c += 128) {
        float v = tf32r(ca1[b * NDIM + c]);
        a0 += v * tf32r(w[c * 2 + 0]);
        a1 += v * tf32r(w[c * 2 + 1]);
    }
    s0[threadIdx.x] = a0; s1[threadIdx.x] = a1;
    __syncthreads();
    for (int off = 64; off > 0; off >>= 1) {
        if (threadIdx.x < off) {
            s0[threadIdx.x] += s0[threadIdx.x + off];
            s1[threadIdx.x] += s1[threadIdx.x + off];
        }
        __syncthreads();
    }
    if (threadIdx.x == 0) {
        out[b * 2 + 0] = s0[0] + bias[0];
        out[b * 2 + 1] = s1[0] + bias[1];
    }
}

// ---------------------------------------------------------------------------
extern "C" void kernel_launch(void* const* d_in, const int* in_sizes, int n_in,
                              void* d_out, int out_size) {
    const int*   cue      = (const int*)d_in[0];     // bool -> int32 in harness
    const float* ec3_last = (const float*)d_in[1];
    const float* ec5_last = (const float*)d_in[2];
    const float* ca1_last = (const float*)d_in[3];
    const float* ca1bias  = (const float*)d_in[4];
    const float* wca3ca1  = (const float*)d_in[5];
    const float* wec3ca1  = (const float*)d_in[6];
    const float* wca1ec5  = (const float*)d_in[7];
    const float* wca1act  = (const float*)d_in[8];
    const float* actbias  = (const float*)d_in[9];
    (void)ca1_last;

    float* out = (float*)d_out;
    float* act = out + OFF_ACT;
    float* e3h = out + OFF_E3H;
    float* e5h = out + OFF_E5H;
    float* c1h = out + OFF_C1H;
    float* ec3 = out + OFF_EC3;
    float* ec5 = out + OFF_EC5;
    float* ca1 = out + OFF_CA1;

    cudaFuncSetAttribute(rnn_persistent, cudaFuncAttributeMaxDynamicSharedMemorySize, SMEM_DYN);

    prep_kernel<<<4197, 256>>>(wec3ca1, wca1ec5, ec3_last, ec5_last, wca3ca1, ec3, ec5);
    rnn_persistent<<<NCTA, 256, SMEM_DYN>>>(ca1bias, cue, ec3, ec5, e3h, e5h, c1h, ca1);
    act_kernel<<<BSZ, 128>>>(ca1, wca1act, actbias, act);
}

// round 17
// speedup vs baseline: 1.0834x; 1.0834x over previous
#include <cuda_runtime.h>
#include <cuda_fp16.h>
#include <stdint.h>

#define BSZ   1024
#define NDIM  1024
#define TLEN  100

// d_out layout (float elements)
#define OFF_ACT 0
#define OFF_E3H 2048
#define OFF_E5H (2048 + 102400)
#define OFF_C1H (2048 + 2*102400)
#define OFF_EC3 (2048 + 3*102400)
#define OFF_EC5 (OFF_EC3 + 1048576)
#define OFF_CA1 (OFF_EC5 + 1048576)

// Activations/weights: k-tile-major swizzled fp16 (validated R15 layout)
__device__ float    g_drive[TLEN * NDIM];
__device__ uint32_t g_keys[2 * TLEN];
__device__ __half   g_wt1[NDIM * NDIM];
__device__ __half   g_wt2[NDIM * NDIM];
__device__ __half   g_at1[NDIM * NDIM];
__device__ __half   g_at2[NDIM * NDIM];

#define KTILES  8
#define SLAB    131072
#define A_BYTES 32768
#define B_BYTES 16384
#define STAGE_BYTES (A_BYTES + B_BYTES)
#define NSTAGE 3
#define SM_BAR  (NSTAGE * STAGE_BYTES)
#define SMEM_DYN (SM_BAR + 64)

__device__ __forceinline__ size_t sw_idx(int row, int col) {
    int kt = col >> 7, c = (col & 127) >> 3, w = col & 7;
    return (size_t)kt * SLAB + (size_t)row * 128 + (size_t)(((c ^ (row & 7)) << 3) + w);
}

// ---------------------------------------------------------------------------
__device__ __forceinline__ float tf32r(float x) {
    uint32_t u = __float_as_uint(x);
    asm("cvt.rna.tf32.f32 %0, %0;" : "+r"(u));
    return __uint_as_float(u);
}
__device__ __forceinline__ float sigmoidf(float x) { return 1.0f / (1.0f + expf(-x)); }
__device__ __forceinline__ uint32_t smem_to_u32(const void* p) {
    uint32_t a;
    asm("{ .reg .u64 t; cvta.to.shared.u64 t, %1; cvt.u32.u64 %0, t; }" : "=r"(a) : "l"(p));
    return a;
}
#define MBARRIER_INIT(mbar, count) \
    asm volatile("mbarrier.init.shared.b64 [%0], %1;" :: "r"((uint32_t)(mbar)), "r"((uint32_t)(count)) : "memory")
#define MBARRIER_EXPECT_TX(mbar, bytes) \
    asm volatile("mbarrier.arrive.expect_tx.shared.b64 _, [%0], %1;" :: "r"((uint32_t)(mbar)), "r"((uint32_t)(bytes)) : "memory")
#define MBARRIER_WAIT_PARITY(mbar, parity) do { \
    uint32_t _m = (uint32_t)(mbar), _p = (uint32_t)(parity), _d; \
    asm volatile("{\n\t.reg .pred p;\n\t" \
        "mbarrier.try_wait.parity.acquire.cta.shared::cta.b64 p, [%1], %2;\n\t" \
        "selp.b32 %0, 1, 0, p;\n\t}" : "=r"(_d) : "r"(_m), "r"(_p) : "memory"); \
    if (!_d) { \
        asm volatile("{\n\t.reg .pred P1;\n\t" \
            "WL_%=:\n\t" \
            "mbarrier.try_wait.parity.acquire.cta.shared::cta.b64 P1, [%0], %1, 0x989680;\n\t" \
            "@P1 bra.uni WD_%=;\n\t" \
            "bra.uni WL_%=;\n\t" \
            "WD_%=:\n\t}" :: "r"(_m), "r"(_p) : "memory"); \
    } \
} while (0)
__device__ __forceinline__ void bulk_g2s(uint32_t dst, const void* src, uint32_t bytes, uint32_t mbar) {
    asm volatile("cp.async.bulk.shared::cta.global.mbarrier::complete_tx::bytes [%0], [%1], %2, [%3];"
        :: "r"(dst), "l"(src), "r"(bytes), "r"(mbar) : "memory");
}
__device__ __forceinline__ void ldsm4(uint32_t r[4], uint32_t addr) {
    asm volatile("ldmatrix.sync.aligned.m8n8.x4.shared.b16 {%0,%1,%2,%3}, [%4];"
        : "=r"(r[0]), "=r"(r[1]), "=r"(r[2]), "=r"(r[3]) : "r"(addr));
}
__device__ __forceinline__ void mma16(float c[4], const uint32_t a[4],
                                      uint32_t b0, uint32_t b1) {
    asm volatile(
        "mma.sync.aligned.m16n8k16.row.col.f32.f16.f16.f32 "
        "{%0,%1,%2,%3}, {%4,%5,%6,%7}, {%8,%9}, {%0,%1,%2,%3};"
        : "+f"(c[0]), "+f"(c[1]), "+f"(c[2]), "+f"(c[3])
        : "r"(a[0]), "r"(a[1]), "r"(a[2]), "r"(a[3]), "r"(b0), "r"(b1));
}

// ---------------------------------------------------------------------------
// Threefry-2x32 (jax partitionable) — validated
// ---------------------------------------------------------------------------
__device__ __forceinline__ void threefry2x32(uint32_t k0, uint32_t k1,
                                             uint32_t x0, uint32_t x1,
                                             uint32_t& o0, uint32_t& o1) {
    uint32_t ks2 = k0 ^ k1 ^ 0x1BD11BDAu;
    x0 += k0; x1 += k1;
#define TF_R(r) { x0 += x1; x1 = __funnelshift_l(x1, x1, (r)); x1 ^= x0; }
    TF_R(13) TF_R(15) TF_R(26) TF_R(6)
    x0 += k1;  x1 += ks2 + 1u;
    TF_R(17) TF_R(29) TF_R(16) TF_R(24)
    x0 += ks2; x1 += k0 + 2u;
    TF_R(13) TF_R(15) TF_R(26) TF_R(6)
    x0 += k0;  x1 += k1 + 3u;
    TF_R(17) TF_R(29) TF_R(16) TF_R(24)
    x0 += k1;  x1 += ks2 + 4u;
    TF_R(13) TF_R(15) TF_R(26) TF_R(6)
    x0 += ks2; x1 += k0 + 5u;
#undef TF_R
    o0 = x0; o1 = x1;
}

__device__ __forceinline__ bool noise_hit(uint32_t k0, uint32_t k1, uint32_t idx) {
    uint32_t o0, o1;
    threefry2x32(k0, k1, 0u, idx, o0, o1);
    uint32_t bits = o0 ^ o1;
    float u = __uint_as_float((bits >> 9) | 0x3f800000u) - 1.0f;
    return u < 0.004f;
}

// ---------------------------------------------------------------------------
// prep kernel: one-time work in one launch. Drive is tiled: 128 blocks,
// 8 t-groups x 16 n-blocks, W tile staged in smem, k ascending (bit-identical).
// ---------------------------------------------------------------------------
#define DRV_T 13
__global__ __launch_bounds__(256) void prep_kernel(
    const float* __restrict__ wec3ca1, const float* __restrict__ wca1ec5,
    const float* __restrict__ ec3_last, const float* __restrict__ ec5_last,
    const float* __restrict__ wca3ca1,
    float* __restrict__ ec3, float* __restrict__ ec5)
{
    __shared__ float ws[128][64];            // 32KB (aliased as transpose tile)
    __shared__ float ca3s[DRV_T][128];       // 6.5KB
    float (*tile)[33] = (float(*)[33])ws;    // transpose path alias (4.2KB < 32KB)

    const int blk = blockIdx.x;
    const int tid = threadIdx.x;

    if (blk < 2048) {                        // weight transposes -> swizzled fp16
        const float* W = (blk < 1024) ? wec3ca1 : wca1ec5;
        __half* dst    = (blk < 1024) ? g_wt1  : g_wt2;
        int b = blk & 1023;
        int bx = (b & 31) * 32, by = (b >> 5) * 32;
        int x = tid & 31, y = tid >> 5;
#pragma unroll
        for (int i = 0; i < 32; i += 8)
            tile[y + i][x] = W[(size_t)(by + y + i) * NDIM + bx + x];
        __syncthreads();
#pragma unroll
        for (int i = 0; i < 32; i += 8) {
            int n = bx + y + i, k = by + x;
            dst[sw_idx(n, k)] = __float2half(tile[x][y + i]);
        }
    } else if (blk < 3072) {                 // ec3 init + swizzled fp16 copy
        int i = ((blk - 2048) * 256 + tid) * 4;
        int m = i >> 10, n = i & 1023;
        float4 v = *(const float4*)(ec3_last + i);
        *(float4*)(ec3 + i) = v;
        g_at1[sw_idx(m, n + 0)] = __float2half(v.x);
        g_at1[sw_idx(m, n + 1)] = __float2half(v.y);
        g_at1[sw_idx(m, n + 2)] = __float2half(v.z);
        g_at1[sw_idx(m, n + 3)] = __float2half(v.w);
    } else if (blk < 4096) {                 // ec5 init
        int i = ((blk - 3072) * 256 + tid) * 4;
        *(float4*)(ec5 + i) = *(const float4*)(ec5_last + i);
    } else if (blk < 4224) {                 // drive tiles
        const int idx = blk - 4096;
        const int tg = idx >> 4, nb = idx & 15;
        const int n0 = nb * 64;
        const int js = tid >> 6, nl = tid & 63;
        float acc[4] = {0.0f, 0.0f, 0.0f, 0.0f};

        for (int k0 = 0; k0 < NDIM; k0 += 128) {
            __syncthreads();
            // stage W[k0:k0+128, n0:n0+64], tf32-rounded
            for (int i = tid; i < 128 * 64; i += 256) {
                int row = i >> 6, col = i & 63;
                ws[row][col] = tf32r(wca3ca1[(size_t)(k0 + row) * NDIM + n0 + col]);
            }
            // stage ca3 values for this t-group
            for (int i = tid; i < DRV_T * 128; i += 256) {
                int j = i >> 7, kk = i & 127;
                int t = tg * DRV_T + j;
                float v = 0.0f;
                if (t < TLEN) {
                    float center = (100.0f / 1023.0f) * (float)(k0 + kk);
                    float d = center - (float)t;
                    v = tf32r(expf(-(d * d) / 50.0f));
                }
                ca3s[j][kk] = v;
            }
            __syncthreads();
            for (int k = 0; k < 128; k++) {
                float w = ws[k][nl];
#pragma unroll
                for (int jj = 0; jj < 4; jj++) {
                    int j = js + 4 * jj;
                    if (j < DRV_T) acc[jj] += ca3s[j][k] * w;
                }
            }
        }
#pragma unroll
        for (int jj = 0; jj < 4; jj++) {
            int j = js + 4 * jj, t = tg * DRV_T + j;
            if (j < DRV_T && t < TLEN) g_drive[t * NDIM + n0 + nl] = acc[jj];
        }
    } else {                                 // keys
        if (tid < TLEN) {
            uint32_t o0, o1;
            threefry2x32(0u, 42u, 0u, (uint32_t)tid, o0, o1);
            g_keys[2 * tid] = o0; g_keys[2 * tid + 1] = o1;
        }
    }
}

// ---------------------------------------------------------------------------
// fp16 GEMM core with TMA bulk loads; NOISE variant computes threefry mask
// in the idle issue slots of the mma wall (validated in R16).
// ---------------------------------------------------------------------------
template<bool NOISE>
__device__ __forceinline__ void gemm_mma_fp16(
    const __half* __restrict__ A, const __half* __restrict__ Bt,
    char* smp, float acc[2][4][4],
    uint32_t nk0, uint32_t nk1, uint32_t& nmask)
{
    const int tid  = threadIdx.x;
    const int lane = tid & 31, warp = tid >> 5;
    const int wm = warp & 3, wn = warp >> 2;
    const int group = lane >> 2, tig = lane & 3;
    const int m0 = blockIdx.y * 128, n0 = blockIdx.x * 64;
    const uint32_t sb = smem_to_u32(smp);
    const uint32_t bar = sb + SM_BAR;

    if (tid == 0) {
        MBARRIER_INIT(bar + 0, 1);
        MBARRIER_INIT(bar + 8, 1);
        MBARRIER_INIT(bar + 16, 1);
    }
    __syncthreads();

    const int q = lane >> 3, r = lane & 7;
    uint32_t abase[2], axr[2];
    const uint32_t aq = (q & 2) ? 1u : 0u;
#pragma unroll
    for (int mi = 0; mi < 2; mi++) {
        int rowA = wm * 32 + mi * 16 + r + ((q & 1) ? 8 : 0);
        abase[mi] = (uint32_t)(rowA * 256);
        axr[mi] = (uint32_t)(rowA & 7);
    }
    uint32_t bbase[2], bxr[2];
    const uint32_t bq = (q & 1) ? 1u : 0u;
#pragma unroll
    for (int j = 0; j < 2; j++) {
        int rowB = wn * 32 + j * 16 + r + ((q & 2) ? 8 : 0);
        bbase[j] = (uint32_t)(A_BYTES + rowB * 256);
        bxr[j] = (uint32_t)(rowB & 7);
    }

#pragma unroll
    for (int mi = 0; mi < 2; mi++)
#pragma unroll
        for (int nj = 0; nj < 4; nj++)
#pragma unroll
            for (int c = 0; c < 4; c++) acc[mi][nj][c] = 0.0f;

    if (tid == 0) {
#pragma unroll
        for (int kt = 0; kt < 2; kt++) {
            uint32_t mb = bar + kt * 8;
            uint32_t st = sb + kt * STAGE_BYTES;
            MBARRIER_EXPECT_TX(mb, STAGE_BYTES);
            bulk_g2s(st,           A  + (size_t)kt * SLAB + (size_t)m0 * 128, A_BYTES, mb);
            bulk_g2s(st + A_BYTES, Bt + (size_t)kt * SLAB + (size_t)n0 * 128, B_BYTES, mb);
        }
    }

    for (int kt = 0; kt < KTILES; kt++) {
        const int s = kt % 3;
        MBARRIER_WAIT_PARITY(bar + s * 8, (kt / 3) & 1);
        const uint32_t st = sb + (uint32_t)s * STAGE_BYTES;

#pragma unroll
        for (int kk = 0; kk < 8; kk++) {
            uint32_t af[2][4], b01[4], b23[4];
            const uint32_t ac = 2 * kk + aq;
            const uint32_t bc = 2 * kk + bq;
            ldsm4(af[0], st + abase[0] + (((ac ^ axr[0]) << 4)));
            ldsm4(af[1], st + abase[1] + (((ac ^ axr[1]) << 4)));
            ldsm4(b01,   st + bbase[0] + (((bc ^ bxr[0]) << 4)));
            ldsm4(b23,   st + bbase[1] + (((bc ^ bxr[1]) << 4)));
#pragma unroll
            for (int mi = 0; mi < 2; mi++) {
                mma16(acc[mi][0], af[mi], b01[0], b01[1]);
                mma16(acc[mi][1], af[mi], b01[2], b01[3]);
                mma16(acc[mi][2], af[mi], b23[0], b23[1]);
                mma16(acc[mi][3], af[mi], b23[2], b23[3]);
            }
        }
        if (NOISE) {
            // 4 threefry hashes per k-tile ride the idle issue slots
#pragma unroll
            for (int h = 0; h < 4; h++) {
                const int e = kt * 4 + h;
                const int mi = e >> 4, nj = (e >> 2) & 3, c = e & 3;
                const int m = m0 + wm * 32 + mi * 16 + group + ((c & 2) ? 8 : 0);
                const int n = n0 + wn * 32 + nj * 8 + tig * 2 + (c & 1);
                if (noise_hit(nk0, nk1, (uint32_t)(m * NDIM + n))) nmask |= (1u << e);
            }
        }
        __syncthreads();
        if (kt + 2 < KTILES && tid == 0) {
            const int kn = kt + 2, sn = kn % 3;
            uint32_t mb = bar + sn * 8;
            uint32_t sd = sb + (uint32_t)sn * STAGE_BYTES;
            MBARRIER_EXPECT_TX(mb, STAGE_BYTES);
            bulk_g2s(sd,           A  + (size_t)kn * SLAB + (size_t)m0 * 128, A_BYTES, mb);
            bulk_g2s(sd + A_BYTES, Bt + (size_t)kn * SLAB + (size_t)n0 * 128, B_BYTES, mb);
        }
    }
}

// ---------------------------------------------------------------------------
// step1: ca1 = relu(drive_t * (1 + sigmoid(ec3 @ wec3ca1)) - ca1bias)
// ---------------------------------------------------------------------------
__global__ __launch_bounds__(256) void step1_mma(
    const float* __restrict__ ca1bias,
    float* __restrict__ ca1, float* __restrict__ c1h, int t, int last)
{
    extern __shared__ char smp[];
    float acc[2][4][4];
    uint32_t dummy = 0;
    gemm_mma_fp16<false>(g_at1, g_wt1, smp, acc, 0u, 0u, dummy);

    const int lane = threadIdx.x & 31, warp = threadIdx.x >> 5;
    const int group = lane >> 2, tig = lane & 3;
    const int wm = warp & 3, wn = warp >> 2;
    const int m0 = blockIdx.y * 128, n0 = blockIdx.x * 64;
    const float* drive = &g_drive[t * NDIM];

#pragma unroll
    for (int mi = 0; mi < 2; mi++)
#pragma unroll
        for (int nj = 0; nj < 4; nj++)
#pragma unroll
            for (int c = 0; c < 4; c++) {
                const int m = m0 + wm * 32 + mi * 16 + group + ((c & 2) ? 8 : 0);
                const int n = n0 + wn * 32 + nj * 8 + tig * 2 + (c & 1);
                float v = fmaxf(drive[n] * (1.0f + sigmoidf(acc[mi][nj][c])) - ca1bias[n], 0.0f);
                if (last) ca1[m * NDIM + n] = v;
                g_at2[sw_idx(m, n)] = __float2half(v);
                if (m == 0) c1h[t * NDIM + n] = v;
            }
}

// ---------------------------------------------------------------------------
// step2: ec5 += ca1 @ wca1ec5; squash; ec3 *= ec5; cue @ t==10; threefry noise
// ---------------------------------------------------------------------------
__global__ __launch_bounds__(256) void step2_mma(
    const int* __restrict__ cue,
    float* __restrict__ ec3, float* __restrict__ ec5,
    float* __restrict__ e3h, float* __restrict__ e5h, int t)
{
    extern __shared__ char smp[];
    float acc[2][4][4];
    const uint32_t k0 = g_keys[2 * t], k1 = g_keys[2 * t + 1];
    uint32_t nmask = 0;
    gemm_mma_fp16<true>(g_at2, g_wt2, smp, acc, k0, k1, nmask);

    const int lane = threadIdx.x & 31, warp = threadIdx.x >> 5;
    const int group = lane >> 2, tig = lane & 3;
    const int wm = warp & 3, wn = warp >> 2;
    const int m0 = blockIdx.y * 128, n0 = blockIdx.x * 64;
    const bool at_cue = (t == 10);

#pragma unroll
    for (int mi = 0; mi < 2; mi++)
#pragma unroll
        for (int nj = 0; nj < 4; nj++)
#pragma unroll
            for (int c = 0; c < 4; c++) {
                const int e = mi * 16 + nj * 4 + c;
                const int m = m0 + wm * 32 + mi * 16 + group + ((c & 2) ? 8 : 0);
                const int n = n0 + wn * 32 + nj * 8 + tig * 2 + (c & 1);
                const int gi = m * NDIM + n;
                float e5 = ec5[gi] + acc[mi][nj][c];       // 10*TS == 1.0 exactly
                e5 = 0.69f + 0.3f * sigmoidf(4.0f * (e5 - 0.3f));
                float e3 = e5 * ec3[gi];
                if (at_cue && (cue[gi] != 0)) e3 = 0.4f * e3 + 0.6f;
                if ((nmask >> e) & 1u) e3 = 0.5f * e3 + 0.3f;
                ec5[gi] = e5;
                ec3[gi] = e3;
                g_at1[sw_idx(m, n)] = __float2half(e3);
                if (m == 0) { e5h[t * NDIM + n] = e5; e3h[t * NDIM + n] = e3; }
            }
}

// ---------------------------------------------------------------------------
// act_cell = ca1 @ wca1act + actbias (tf32 operands, validated)
// ---------------------------------------------------------------------------
__global__ __launch_bounds__(128) void act_kernel(
    const float* __restrict__ ca1, const float* __restrict__ w,
    const float* __restrict__ bias, float* __restrict__ out)
{
    __shared__ float s0[128], s1[128];
    const int b = blockIdx.x;
    float a0 = 0.0f, a1 = 0.0f;
    for (int c = threadIdx.x; c < NDIM; c += 128) {
        float v = tf32r(ca1[b * NDIM + c]);
        a0 += v * tf32r(w[c * 2 + 0]);
        a1 += v * tf32r(w[c * 2 + 1]);
    }
    s0[threadIdx.x] = a0; s1[threadIdx.x] = a1;
    __syncthreads();
    for (int off = 64; off > 0; off >>= 1) {
        if (threadIdx.x < off) {
            s0[threadIdx.x] += s0[threadIdx.x + off];
            s1[threadIdx.x] += s1[threadIdx.x + off];
        }
        __syncthreads();
    }
    if (threadIdx.x == 0) {
        out[b * 2 + 0] = s0[0] + bias[0];
        out[b * 2 + 1] = s1[0] + bias[1];
    }
}

// ---------------------------------------------------------------------------
extern "C" void kernel_launch(void* const* d_in, const int* in_sizes, int n_in,
                              void* d_out, int out_size) {
    const int*   cue      = (const int*)d_in[0];     // bool -> int32 in harness
    const float* ec3_last = (const float*)d_in[1];
    const float* ec5_last = (const float*)d_in[2];
    const float* ca1_last = (const float*)d_in[3];
    const float* ca1bias  = (const float*)d_in[4];
    const float* wca3ca1  = (const float*)d_in[5];
    const float* wec3ca1  = (const float*)d_in[6];
    const float* wca1ec5  = (const float*)d_in[7];
    const float* wca1act  = (const float*)d_in[8];
    const float* actbias  = (const float*)d_in[9];
    (void)ca1_last;

    float* out = (float*)d_out;
    float* act = out + OFF_ACT;
    float* e3h = out + OFF_E3H;
    float* e5h = out + OFF_E5H;
    float* c1h = out + OFF_C1H;
    float* ec3 = out + OFF_EC3;
    float* ec5 = out + OFF_EC5;
    float* ca1 = out + OFF_CA1;

    cudaFuncSetAttribute(step1_mma, cudaFuncAttributeMaxDynamicSharedMemorySize, SMEM_DYN);
    cudaFuncSetAttribute(step2_mma, cudaFuncAttributeMaxDynamicSharedMemorySize, SMEM_DYN);

    prep_kernel<<<4225, 256>>>(wec3ca1, wca1ec5, ec3_last, ec5_last, wca3ca1, ec3, ec5);

    dim3 grid(NDIM / 64, BSZ / 128);       // 16 x 8 = 128 CTAs
    for (int t = 0; t < TLEN; t++) {
        step1_mma<<<grid, 256, SMEM_DYN>>>(ca1bias, ca1, c1h, t, t == TLEN - 1);
        step2_mma<<<grid, 256, SMEM_DYN>>>(cue, ec3, ec5, e3h, e5h, t);
    }
    act_kernel<<<BSZ, 128>>>(ca1, wca1act, actbias, act);
}